// round 6
// baseline (speedup 1.0000x reference)
#include <cuda_runtime.h>
#include <cuda_bf16.h>
#include <cstdint>

#define kN 100000
#define kE 1600000
#define kQ 500000
#define kD 256

// ============================ static scratch ============================
__device__ __align__(16) float g_dinv[kN];
__device__ __align__(16) float g_h[(size_t)kN * kD];
__device__ __align__(16) float g_y[(size_t)kN * kD];
__device__ __align__(16) __nv_bfloat16 g_x_hi[(size_t)kN * kD];
__device__ __align__(16) __nv_bfloat16 g_x_lo[(size_t)kN * kD];
__device__ __align__(16) __nv_bfloat16 g_qa_hi[(size_t)kQ * kD];
__device__ __align__(16) __nv_bfloat16 g_qa_lo[(size_t)kQ * kD];
__device__ __align__(16) __nv_bfloat16 g_qb_hi[(size_t)kQ * kD];
__device__ __align__(16) __nv_bfloat16 g_qb_lo[(size_t)kQ * kD];
__device__ __align__(16) __nv_bfloat16 g_wt_hi[5 * kD * kD];  // W^T (N-major) for W0,W1,W2,P0,P1
__device__ __align__(16) __nv_bfloat16 g_wt_lo[5 * kD * kD];

__device__ __forceinline__ void split2(float v, __nv_bfloat16& hi, __nv_bfloat16& lo) {
    hi = __float2bfloat16(v);
    lo = __float2bfloat16(v - __bfloat162float(hi));
}

// ============================ PTX helpers (generic compute_103-safe) ============================
__device__ __forceinline__ uint32_t smem_to_u32(const void* p) {
    uint32_t a;
    asm("{ .reg .u64 t; cvta.to.shared.u64 t, %1; cvt.u32.u64 %0, t; }" : "=r"(a) : "l"(p));
    return a;
}
__device__ __forceinline__ void cp16(uint32_t dst, const void* src, int sz) {
    asm volatile("cp.async.cg.shared.global [%0], [%1], 16, %2;"
                 :: "r"(dst), "l"(src), "r"(sz) : "memory");
}
#define CP_COMMIT() asm volatile("cp.async.commit_group;" ::: "memory")
#define CP_WAIT(n)  asm volatile("cp.async.wait_group %0;" :: "n"(n) : "memory")

__device__ __forceinline__ void ldsm_x4(uint32_t* r, uint32_t addr) {
    asm volatile("ldmatrix.sync.aligned.m8n8.x4.shared.b16 {%0,%1,%2,%3}, [%4];"
                 : "=r"(r[0]), "=r"(r[1]), "=r"(r[2]), "=r"(r[3]) : "r"(addr));
}
__device__ __forceinline__ void mma16816(float* c, const uint32_t* a, const uint32_t* b) {
    asm volatile(
        "mma.sync.aligned.m16n8k16.row.col.f32.bf16.bf16.f32 "
        "{%0,%1,%2,%3}, {%4,%5,%6,%7}, {%8,%9}, {%0,%1,%2,%3};"
        : "+f"(c[0]), "+f"(c[1]), "+f"(c[2]), "+f"(c[3])
        : "r"(a[0]), "r"(a[1]), "r"(a[2]), "r"(a[3]), "r"(b[0]), "r"(b[1]));
}

// ============================ degree / norm ============================
__global__ void k_deg_init() {
    int i = blockIdx.x * blockDim.x + threadIdx.x;
    if (i < kN) g_dinv[i] = 1.0f;
}
__global__ void k_deg_count(const int* __restrict__ row) {
    int e = blockIdx.x * blockDim.x + threadIdx.x;
    if (e < kE) atomicAdd(&g_dinv[row[e]], 1.0f);
}
__global__ void k_dinv() {
    int i = blockIdx.x * blockDim.x + threadIdx.x;
    if (i < kN) g_dinv[i] = rsqrtf(g_dinv[i]);
}

// ============================ weight transpose+split ============================
__global__ void k_conv_w(const float* __restrict__ W0, const float* __restrict__ W1,
                         const float* __restrict__ W2, const float* __restrict__ P0,
                         const float* __restrict__ P1) {
    int t = blockIdx.x * blockDim.x + threadIdx.x;
    if (t >= 5 * kD * kD) return;
    int w = t >> 16;
    int i = t & 0xFFFF;
    int n = i >> 8, k = i & 255;
    const float* Ws[5] = {W0, W1, W2, P0, P1};
    float v = Ws[w][k * kD + n];
    __nv_bfloat16 hi, lo;
    split2(v, hi, lo);
    g_wt_hi[t] = hi;
    g_wt_lo[t] = lo;
}

// ============================ emb -> hi/lo ============================
__global__ void k_conv_emb(const float* __restrict__ emb) {
    long long idx = (long long)blockIdx.x * blockDim.x + threadIdx.x;
    if (idx >= (long long)kN * 64) return;
    float4 v = ((const float4*)emb)[idx];
    __nv_bfloat16 h0, h1, h2, h3, l0, l1, l2, l3;
    split2(v.x, h0, l0); split2(v.y, h1, l1); split2(v.z, h2, l2); split2(v.w, h3, l3);
    __nv_bfloat162* ph = (__nv_bfloat162*)g_x_hi;
    __nv_bfloat162* pl = (__nv_bfloat162*)g_x_lo;
    ph[idx * 2]     = __halves2bfloat162(h0, h1);
    ph[idx * 2 + 1] = __halves2bfloat162(h2, h3);
    pl[idx * 2]     = __halves2bfloat162(l0, l1);
    pl[idx * 2 + 1] = __halves2bfloat162(l2, l3);
}

// ============================ bf16-split tensor-core GEMM (mma.sync) ============================
// C[M,256] = (Ahi+Alo)[M,256] @ W[256,256], W given transposed hi/lo as [N][K].
// CTA tile 128x128, BK=32, 2-stage cp.async pipeline, 256 threads (2x4 warps).
// mode 0: fp32 out (Cf). mode 1: bias+relu -> bf16 hi/lo out (Chi/Clo).
#define BM 128
#define BN 128
#define BK 32
#define STRIDE 40                      // bf16 elems per smem row (32 + 8 pad; keeps 16B align, conflict-free ldsm)
#define TILE_ELE (128 * STRIDE)        // 5120 elems per tile
#define STAGE_ELE (4 * TILE_ELE)       // Ahi,Alo,Bhi,Blo
#define SMEM_BYTES (2 * STAGE_ELE * 2) // 81920

__device__ __forceinline__ void load_tiles(
    uint32_t sbase, int stage,
    const __nv_bfloat16* __restrict__ Ahi, const __nv_bfloat16* __restrict__ Alo,
    const __nv_bfloat16* __restrict__ Bhi, const __nv_bfloat16* __restrict__ Blo,
    int m0, int n0, int M, int k0, int tid) {
    int row = tid >> 2, ch = tid & 3;
#pragma unroll
    for (int i = 0; i < 2; i++) {
        int r = row + i * 64;
        uint32_t so = sbase + (uint32_t)(stage * STAGE_ELE + r * STRIDE + ch * 8) * 2;
        size_t goff = (size_t)(m0 + r) * kD + k0 + ch * 8;
        int sz = ((m0 + r) < M) ? 16 : 0;
        cp16(so,                    Ahi + goff, sz);
        cp16(so + TILE_ELE * 2,     Alo + goff, sz);
        size_t boff = (size_t)(n0 + r) * kD + k0 + ch * 8;
        cp16(so + 2 * TILE_ELE * 2, Bhi + boff, 16);
        cp16(so + 3 * TILE_ELE * 2, Blo + boff, 16);
    }
}

__global__ void __launch_bounds__(256, 1)
k_tc_gemm(const __nv_bfloat16* __restrict__ Ahi, const __nv_bfloat16* __restrict__ Alo,
          const __nv_bfloat16* __restrict__ Bhi, const __nv_bfloat16* __restrict__ Blo,
          int M, const float* __restrict__ bias, int mode,
          float* __restrict__ Cf, __nv_bfloat16* __restrict__ Chi, __nv_bfloat16* __restrict__ Clo) {
    extern __shared__ __nv_bfloat16 sm[];
    const uint32_t sbase = smem_to_u32(sm);
    const int tid = threadIdx.x;
    const int lane = tid & 31;
    const int wid = tid >> 5;
    const int wm = wid >> 2;            // 0..1  (64 rows each)
    const int wn = wid & 3;             // 0..3  (32 cols each)
    const int m0 = blockIdx.x * BM;
    const int n0 = blockIdx.y * BN;

    float acc[64];
#pragma unroll
    for (int i = 0; i < 64; i++) acc[i] = 0.f;

    load_tiles(sbase, 0, Ahi, Alo, Bhi, Blo, m0, n0, M, 0, tid);
    CP_COMMIT();

    for (int it = 0; it < 8; it++) {
        if (it < 7) {
            load_tiles(sbase, (it + 1) & 1, Ahi, Alo, Bhi, Blo, m0, n0, M, (it + 1) * BK, tid);
            CP_COMMIT();
            CP_WAIT(1);
        } else {
            CP_WAIT(0);
        }
        __syncthreads();

        const int stage = it & 1;
        const uint32_t sA = sbase + (uint32_t)(stage * STAGE_ELE) * 2;
        const uint32_t sB = sA + 2 * TILE_ELE * 2;

#pragma unroll
        for (int ks = 0; ks < 2; ks++) {
            const int kb = ks * 16;
            uint32_t bh[8], bl[8];
#pragma unroll
            for (int h2 = 0; h2 < 2; h2++) {
                int n = wn * 32 + h2 * 16 + (lane & 7) + ((lane >> 4) << 3);
                int kk = kb + (((lane >> 3) & 1) << 3);
                uint32_t ad = sB + (uint32_t)(n * STRIDE + kk) * 2;
                ldsm_x4(&bh[h2 * 4], ad);
                ldsm_x4(&bl[h2 * 4], ad + TILE_ELE * 2);
            }
#pragma unroll
            for (int mt = 0; mt < 4; mt++) {
                int m = wm * 64 + mt * 16 + (lane & 15);
                int kk = kb + ((lane >> 4) << 3);
                uint32_t aad = sA + (uint32_t)(m * STRIDE + kk) * 2;
                uint32_t ah[4], al[4];
                ldsm_x4(ah, aad);
                ldsm_x4(al, aad + TILE_ELE * 2);
#pragma unroll
                for (int nt = 0; nt < 4; nt++) {
                    float* c = &acc[(mt * 4 + nt) * 4];
                    mma16816(c, ah, &bh[nt * 2]);
                    mma16816(c, ah, &bl[nt * 2]);
                    mma16816(c, al, &bh[nt * 2]);
                }
            }
        }
        __syncthreads();
    }

    // ---- epilogue ----
#pragma unroll
    for (int mt = 0; mt < 4; mt++) {
        int r0 = m0 + wm * 64 + mt * 16 + (lane >> 2);
        int r1 = r0 + 8;
#pragma unroll
        for (int nt = 0; nt < 4; nt++) {
            const float* c = &acc[(mt * 4 + nt) * 4];
            int cb = n0 + wn * 32 + nt * 8 + ((lane & 3) << 1);
            if (mode == 0) {
                if (r0 < M) *(float2*)(Cf + (size_t)r0 * kD + cb) = make_float2(c[0], c[1]);
                if (r1 < M) *(float2*)(Cf + (size_t)r1 * kD + cb) = make_float2(c[2], c[3]);
            } else {
                float bv0 = bias[cb], bv1 = bias[cb + 1];
                if (r0 < M) {
                    float v0 = fmaxf(c[0] + bv0, 0.f), v1 = fmaxf(c[1] + bv1, 0.f);
                    __nv_bfloat16 h0, l0, h1, l1;
                    split2(v0, h0, l0); split2(v1, h1, l1);
                    *(__nv_bfloat162*)(Chi + (size_t)r0 * kD + cb) = __halves2bfloat162(h0, h1);
                    *(__nv_bfloat162*)(Clo + (size_t)r0 * kD + cb) = __halves2bfloat162(l0, l1);
                }
                if (r1 < M) {
                    float v0 = fmaxf(c[2] + bv0, 0.f), v1 = fmaxf(c[3] + bv1, 0.f);
                    __nv_bfloat16 h0, l0, h1, l1;
                    split2(v0, h0, l0); split2(v1, h1, l1);
                    *(__nv_bfloat162*)(Chi + (size_t)r1 * kD + cb) = __halves2bfloat162(h0, h1);
                    *(__nv_bfloat162*)(Clo + (size_t)r1 * kD + cb) = __halves2bfloat162(l0, l1);
                }
            }
        }
    }
}

// ============================ aggregation ============================
__global__ void k_agg_init(const float* __restrict__ b) {
    long long idx = (long long)blockIdx.x * blockDim.x + threadIdx.x;
    if (idx >= (long long)kN * 64) return;
    int i = (int)(idx >> 6);
    int d4 = (int)(idx & 63);
    float s = g_dinv[i]; s = s * s;
    float4 h4 = ((const float4*)g_h)[idx];
    float4 b4 = ((const float4*)b)[d4];
    ((float4*)g_y)[idx] = make_float4(h4.x * s + b4.x, h4.y * s + b4.y,
                                      h4.z * s + b4.z, h4.w * s + b4.w);
}

__global__ void k_agg_edges(const int* __restrict__ row, const int* __restrict__ col) {
    long long t = (long long)blockIdx.x * blockDim.x + threadIdx.x;
    int e = (int)(t >> 5);
    int lane = (int)(t & 31);
    if (e >= kE) return;
    int r = row[e], c = col[e];
    float nrm = g_dinv[r] * g_dinv[c];
    const float4* hp = (const float4*)(g_h + (size_t)c * kD);
    float4* yp = (float4*)(g_y + (size_t)r * kD);
#pragma unroll
    for (int j = 0; j < 2; j++) {
        float4 v = hp[lane + j * 32];
        float4 mv = make_float4(v.x * nrm, v.y * nrm, v.z * nrm, v.w * nrm);
        atomicAdd(yp + lane + j * 32, mv);
    }
}

__global__ void k_relu_split() {
    long long idx = (long long)blockIdx.x * blockDim.x + threadIdx.x;
    if (idx >= (long long)kN * 64) return;
    float4 v = ((const float4*)g_y)[idx];
    v.x = fmaxf(v.x, 0.f); v.y = fmaxf(v.y, 0.f);
    v.z = fmaxf(v.z, 0.f); v.w = fmaxf(v.w, 0.f);
    __nv_bfloat16 h0, h1, h2, h3, l0, l1, l2, l3;
    split2(v.x, h0, l0); split2(v.y, h1, l1); split2(v.z, h2, l2); split2(v.w, h3, l3);
    __nv_bfloat162* ph = (__nv_bfloat162*)g_x_hi;
    __nv_bfloat162* pl = (__nv_bfloat162*)g_x_lo;
    ph[idx * 2]     = __halves2bfloat162(h0, h1);
    ph[idx * 2 + 1] = __halves2bfloat162(h2, h3);
    pl[idx * 2]     = __halves2bfloat162(l0, l1);
    pl[idx * 2 + 1] = __halves2bfloat162(l2, l3);
}

// ============================ query gather (x[e0]*x[e1] -> hi/lo) ============================
__global__ void k_gather(const int* __restrict__ e0, const int* __restrict__ e1) {
    long long idx = (long long)blockIdx.x * blockDim.x + threadIdx.x;
    if (idx >= (long long)kQ * 64) return;
    int q = (int)(idx >> 6);
    int d4 = (int)(idx & 63);
    int a = e0[q], b = e1[q];
    float4 xa = ((const float4*)g_y)[(size_t)a * 64 + d4];
    float4 xb = ((const float4*)g_y)[(size_t)b * 64 + d4];
    float4 p = make_float4(xa.x * xb.x, xa.y * xb.y, xa.z * xb.z, xa.w * xb.w);
    __nv_bfloat16 h0, h1, h2, h3, l0, l1, l2, l3;
    split2(p.x, h0, l0); split2(p.y, h1, l1); split2(p.z, h2, l2); split2(p.w, h3, l3);
    __nv_bfloat162* ph = (__nv_bfloat162*)g_qa_hi;
    __nv_bfloat162* pl = (__nv_bfloat162*)g_qa_lo;
    ph[idx * 2]     = __halves2bfloat162(h0, h1);
    ph[idx * 2 + 1] = __halves2bfloat162(h2, h3);
    pl[idx * 2]     = __halves2bfloat162(l0, l1);
    pl[idx * 2 + 1] = __halves2bfloat162(l2, l3);
}

// ============================ final dot + sigmoid ============================
__global__ void k_final(const float* __restrict__ P2, const float* __restrict__ pb2,
                        float* __restrict__ out) {
    long long t = (long long)blockIdx.x * blockDim.x + threadIdx.x;
    int q = (int)(t >> 5);
    int lane = (int)(t & 31);
    if (q >= kQ) return;
    uint4 hv = ((const uint4*)(g_qa_hi + (size_t)q * kD))[lane];
    uint4 lv = ((const uint4*)(g_qa_lo + (size_t)q * kD))[lane];
    const float4* wp = (const float4*)P2;
    float4 w0 = wp[lane * 2], w1 = wp[lane * 2 + 1];
    const __nv_bfloat162* h2 = (const __nv_bfloat162*)&hv;
    const __nv_bfloat162* l2 = (const __nv_bfloat162*)&lv;
    float s = 0.f;
    float2 a;
    a = __bfloat1622float2(h2[0]); { float2 b = __bfloat1622float2(l2[0]); a.x += b.x; a.y += b.y; }
    s = fmaf(a.x, w0.x, s); s = fmaf(a.y, w0.y, s);
    a = __bfloat1622float2(h2[1]); { float2 b = __bfloat1622float2(l2[1]); a.x += b.x; a.y += b.y; }
    s = fmaf(a.x, w0.z, s); s = fmaf(a.y, w0.w, s);
    a = __bfloat1622float2(h2[2]); { float2 b = __bfloat1622float2(l2[2]); a.x += b.x; a.y += b.y; }
    s = fmaf(a.x, w1.x, s); s = fmaf(a.y, w1.y, s);
    a = __bfloat1622float2(h2[3]); { float2 b = __bfloat1622float2(l2[3]); a.x += b.x; a.y += b.y; }
    s = fmaf(a.x, w1.z, s); s = fmaf(a.y, w1.w, s);
#pragma unroll
    for (int o = 16; o > 0; o >>= 1) s += __shfl_down_sync(0xffffffffu, s, o);
    if (lane == 0) out[q] = 1.f / (1.f + expf(-(s + pb2[0])));
}

// ============================ launch ============================
extern "C" void kernel_launch(void* const* d_in, const int* in_sizes, int n_in,
                              void* d_out, int out_size) {
    const int*   adj_row = (const int*)d_in[0];
    const int*   adj_col = (const int*)d_in[1];
    const int*   edges   = (const int*)d_in[2];
    const float* emb     = (const float*)d_in[3];
    const float* W0 = (const float*)d_in[4];  const float* b0 = (const float*)d_in[5];
    const float* W1 = (const float*)d_in[6];  const float* b1 = (const float*)d_in[7];
    const float* W2 = (const float*)d_in[8];  const float* b2 = (const float*)d_in[9];
    const float* P0 = (const float*)d_in[10]; const float* pb0 = (const float*)d_in[11];
    const float* P1 = (const float*)d_in[12]; const float* pb1 = (const float*)d_in[13];
    const float* P2 = (const float*)d_in[14]; const float* pb2 = (const float*)d_in[15];
    float* out = (float*)d_out;

    cudaFuncSetAttribute(k_tc_gemm, cudaFuncAttributeMaxDynamicSharedMemorySize, SMEM_BYTES);

    float* dH;
    __nv_bfloat16 *dXh, *dXl, *dQah, *dQal, *dQbh, *dQbl, *dWth, *dWtl;
    cudaGetSymbolAddress((void**)&dH,   g_h);
    cudaGetSymbolAddress((void**)&dXh,  g_x_hi);
    cudaGetSymbolAddress((void**)&dXl,  g_x_lo);
    cudaGetSymbolAddress((void**)&dQah, g_qa_hi);
    cudaGetSymbolAddress((void**)&dQal, g_qa_lo);
    cudaGetSymbolAddress((void**)&dQbh, g_qb_hi);
    cudaGetSymbolAddress((void**)&dQbl, g_qb_lo);
    cudaGetSymbolAddress((void**)&dWth, g_wt_hi);
    cudaGetSymbolAddress((void**)&dWtl, g_wt_lo);

    const int TB = 256;
    k_deg_init<<<(kN + TB - 1) / TB, TB>>>();
    k_deg_count<<<(kE + TB - 1) / TB, TB>>>(adj_row);
    k_dinv<<<(kN + TB - 1) / TB, TB>>>();
    k_conv_w<<<(5 * kD * kD + TB - 1) / TB, TB>>>(W0, W1, W2, P0, P1);

    long long nEl = (long long)kN * 64;
    int gElem = (int)((nEl + TB - 1) / TB);
    int gEdge = (int)(((long long)kE * 32 + TB - 1) / TB);
    k_conv_emb<<<gElem, TB>>>(emb);

    dim3 gN((kN + BM - 1) / BM, 2);
    dim3 gQ((kQ + BM - 1) / BM, 2);
    const float* biasN[3] = {b0, b1, b2};

    for (int l = 0; l < 3; l++) {
        k_tc_gemm<<<gN, 256, SMEM_BYTES>>>(dXh, dXl, dWth + l * kD * kD, dWtl + l * kD * kD,
                                           kN, nullptr, 0, dH, nullptr, nullptr);
        k_agg_init<<<gElem, TB>>>(biasN[l]);
        k_agg_edges<<<gEdge, TB>>>(adj_row, adj_col);
        if (l < 2) k_relu_split<<<gElem, TB>>>();
    }

    long long qEl = (long long)kQ * 64;
    int gQel = (int)((qEl + TB - 1) / TB);
    k_gather<<<gQel, TB>>>(edges, edges + kQ);

    k_tc_gemm<<<gQ, 256, SMEM_BYTES>>>(dQah, dQal, dWth + 3 * kD * kD, dWtl + 3 * kD * kD,
                                       kQ, pb0, 1, nullptr, dQbh, dQbl);
    k_tc_gemm<<<gQ, 256, SMEM_BYTES>>>(dQbh, dQbl, dWth + 4 * kD * kD, dWtl + 4 * kD * kD,
                                       kQ, pb1, 1, nullptr, dQah, dQal);

    int gFin = (int)(((long long)kQ * 32 + TB - 1) / TB);
    k_final<<<gFin, TB>>>(P2, pb2, out);
}

// round 7
// speedup vs baseline: 1.0013x; 1.0013x over previous
#include <cuda_runtime.h>
#include <cuda_bf16.h>
#include <cstdint>

#define kN 100000
#define kE 1600000
#define kQ 500000
#define kD 256

// ============================ static scratch ============================
__device__ __align__(16) float g_dinv[kN];
__device__ __align__(16) float g_h[(size_t)kN * kD];
__device__ __align__(16) float g_y[(size_t)kN * kD];
__device__ __align__(16) __nv_bfloat16 g_x_hi[(size_t)kN * kD];
__device__ __align__(16) __nv_bfloat16 g_x_lo[(size_t)kN * kD];
__device__ __align__(16) __nv_bfloat16 g_qa_hi[(size_t)kQ * kD];
__device__ __align__(16) __nv_bfloat16 g_qa_lo[(size_t)kQ * kD];
__device__ __align__(16) __nv_bfloat16 g_qb_hi[(size_t)kQ * kD];
__device__ __align__(16) __nv_bfloat16 g_qb_lo[(size_t)kQ * kD];
__device__ __align__(16) __nv_bfloat16 g_wt_hi[5 * kD * kD];  // W^T (N-major) for W0,W1,W2,P0,P1
__device__ __align__(16) __nv_bfloat16 g_wt_lo[5 * kD * kD];

__device__ __forceinline__ void split2(float v, __nv_bfloat16& hi, __nv_bfloat16& lo) {
    hi = __float2bfloat16(v);
    lo = __float2bfloat16(v - __bfloat162float(hi));
}

// ============================ PTX helpers (generic compute_103-safe) ============================
__device__ __forceinline__ uint32_t smem_to_u32(const void* p) {
    uint32_t a;
    asm("{ .reg .u64 t; cvta.to.shared.u64 t, %1; cvt.u32.u64 %0, t; }" : "=r"(a) : "l"(p));
    return a;
}
__device__ __forceinline__ void cp16(uint32_t dst, const void* src, int sz) {
    asm volatile("cp.async.cg.shared.global [%0], [%1], 16, %2;"
                 :: "r"(dst), "l"(src), "r"(sz) : "memory");
}
#define CP_COMMIT() asm volatile("cp.async.commit_group;" ::: "memory")
#define CP_WAIT(n)  asm volatile("cp.async.wait_group %0;" :: "n"(n) : "memory")

__device__ __forceinline__ void ldsm_x4(uint32_t* r, uint32_t addr) {
    asm volatile("ldmatrix.sync.aligned.m8n8.x4.shared.b16 {%0,%1,%2,%3}, [%4];"
                 : "=r"(r[0]), "=r"(r[1]), "=r"(r[2]), "=r"(r[3]) : "r"(addr));
}
__device__ __forceinline__ void mma16816(float* c, const uint32_t* a, const uint32_t* b) {
    asm volatile(
        "mma.sync.aligned.m16n8k16.row.col.f32.bf16.bf16.f32 "
        "{%0,%1,%2,%3}, {%4,%5,%6,%7}, {%8,%9}, {%0,%1,%2,%3};"
        : "+f"(c[0]), "+f"(c[1]), "+f"(c[2]), "+f"(c[3])
        : "r"(a[0]), "r"(a[1]), "r"(a[2]), "r"(a[3]), "r"(b[0]), "r"(b[1]));
}

// ============================ degree / norm ============================
__global__ void k_deg_init() {
    int i = blockIdx.x * blockDim.x + threadIdx.x;
    if (i < kN) g_dinv[i] = 1.0f;
}
__global__ void k_deg_count(const int* __restrict__ row) {
    int e = blockIdx.x * blockDim.x + threadIdx.x;
    if (e < kE) atomicAdd(&g_dinv[row[e]], 1.0f);
}
__global__ void k_dinv() {
    int i = blockIdx.x * blockDim.x + threadIdx.x;
    if (i < kN) g_dinv[i] = rsqrtf(g_dinv[i]);
}

// ============================ weight transpose+split ============================
__global__ void k_conv_w(const float* __restrict__ W0, const float* __restrict__ W1,
                         const float* __restrict__ W2, const float* __restrict__ P0,
                         const float* __restrict__ P1) {
    int t = blockIdx.x * blockDim.x + threadIdx.x;
    if (t >= 5 * kD * kD) return;
    int w = t >> 16;
    int i = t & 0xFFFF;
    int n = i >> 8, k = i & 255;
    const float* Ws[5] = {W0, W1, W2, P0, P1};
    float v = Ws[w][k * kD + n];
    __nv_bfloat16 hi, lo;
    split2(v, hi, lo);
    g_wt_hi[t] = hi;
    g_wt_lo[t] = lo;
}

// ============================ emb -> hi/lo ============================
__global__ void k_conv_emb(const float* __restrict__ emb) {
    long long idx = (long long)blockIdx.x * blockDim.x + threadIdx.x;
    if (idx >= (long long)kN * 64) return;
    float4 v = ((const float4*)emb)[idx];
    __nv_bfloat16 h0, h1, h2, h3, l0, l1, l2, l3;
    split2(v.x, h0, l0); split2(v.y, h1, l1); split2(v.z, h2, l2); split2(v.w, h3, l3);
    __nv_bfloat162* ph = (__nv_bfloat162*)g_x_hi;
    __nv_bfloat162* pl = (__nv_bfloat162*)g_x_lo;
    ph[idx * 2]     = __halves2bfloat162(h0, h1);
    ph[idx * 2 + 1] = __halves2bfloat162(h2, h3);
    pl[idx * 2]     = __halves2bfloat162(l0, l1);
    pl[idx * 2 + 1] = __halves2bfloat162(l2, l3);
}

// ============================ bf16-split tensor-core GEMM (mma.sync) ============================
// C[M,256] = (Ahi+Alo)[M,256] @ W[256,256], W given transposed hi/lo as [N][K].
// CTA tile 128x128, BK=32, 2-stage cp.async pipeline, 256 threads (2x4 warps).
// mode 0: fp32 out (Cf). mode 1: bias+relu -> bf16 hi/lo out (Chi/Clo).
#define BM 128
#define BN 128
#define BK 32
#define STRIDE 40                      // bf16 elems per smem row (32 + 8 pad; keeps 16B align, conflict-free ldsm)
#define TILE_ELE (128 * STRIDE)        // 5120 elems per tile
#define STAGE_ELE (4 * TILE_ELE)       // Ahi,Alo,Bhi,Blo
#define SMEM_BYTES (2 * STAGE_ELE * 2) // 81920

__device__ __forceinline__ void load_tiles(
    uint32_t sbase, int stage,
    const __nv_bfloat16* __restrict__ Ahi, const __nv_bfloat16* __restrict__ Alo,
    const __nv_bfloat16* __restrict__ Bhi, const __nv_bfloat16* __restrict__ Blo,
    int m0, int n0, int M, int k0, int tid) {
    int row = tid >> 2, ch = tid & 3;
#pragma unroll
    for (int i = 0; i < 2; i++) {
        int r = row + i * 64;
        uint32_t so = sbase + (uint32_t)(stage * STAGE_ELE + r * STRIDE + ch * 8) * 2;
        size_t goff = (size_t)(m0 + r) * kD + k0 + ch * 8;
        int sz = ((m0 + r) < M) ? 16 : 0;
        cp16(so,                    Ahi + goff, sz);
        cp16(so + TILE_ELE * 2,     Alo + goff, sz);
        size_t boff = (size_t)(n0 + r) * kD + k0 + ch * 8;
        cp16(so + 2 * TILE_ELE * 2, Bhi + boff, 16);
        cp16(so + 3 * TILE_ELE * 2, Blo + boff, 16);
    }
}

__global__ void __launch_bounds__(256, 1)
k_tc_gemm(const __nv_bfloat16* __restrict__ Ahi, const __nv_bfloat16* __restrict__ Alo,
          const __nv_bfloat16* __restrict__ Bhi, const __nv_bfloat16* __restrict__ Blo,
          int M, const float* __restrict__ bias, int mode,
          float* __restrict__ Cf, __nv_bfloat16* __restrict__ Chi, __nv_bfloat16* __restrict__ Clo) {
    extern __shared__ __nv_bfloat16 sm[];
    const uint32_t sbase = smem_to_u32(sm);
    const int tid = threadIdx.x;
    const int lane = tid & 31;
    const int wid = tid >> 5;
    const int wm = wid >> 2;            // 0..1  (64 rows each)
    const int wn = wid & 3;             // 0..3  (32 cols each)
    const int m0 = blockIdx.x * BM;
    const int n0 = blockIdx.y * BN;

    float acc[64];
#pragma unroll
    for (int i = 0; i < 64; i++) acc[i] = 0.f;

    load_tiles(sbase, 0, Ahi, Alo, Bhi, Blo, m0, n0, M, 0, tid);
    CP_COMMIT();

    for (int it = 0; it < 8; it++) {
        if (it < 7) {
            load_tiles(sbase, (it + 1) & 1, Ahi, Alo, Bhi, Blo, m0, n0, M, (it + 1) * BK, tid);
            CP_COMMIT();
            CP_WAIT(1);
        } else {
            CP_WAIT(0);
        }
        __syncthreads();

        const int stage = it & 1;
        const uint32_t sA = sbase + (uint32_t)(stage * STAGE_ELE) * 2;
        const uint32_t sB = sA + 2 * TILE_ELE * 2;

#pragma unroll
        for (int ks = 0; ks < 2; ks++) {
            const int kb = ks * 16;
            uint32_t bh[8], bl[8];
#pragma unroll
            for (int h2 = 0; h2 < 2; h2++) {
                int n = wn * 32 + h2 * 16 + (lane & 7) + ((lane >> 4) << 3);
                int kk = kb + (((lane >> 3) & 1) << 3);
                uint32_t ad = sB + (uint32_t)(n * STRIDE + kk) * 2;
                ldsm_x4(&bh[h2 * 4], ad);
                ldsm_x4(&bl[h2 * 4], ad + TILE_ELE * 2);
            }
#pragma unroll
            for (int mt = 0; mt < 4; mt++) {
                int m = wm * 64 + mt * 16 + (lane & 15);
                int kk = kb + ((lane >> 4) << 3);
                uint32_t aad = sA + (uint32_t)(m * STRIDE + kk) * 2;
                uint32_t ah[4], al[4];
                ldsm_x4(ah, aad);
                ldsm_x4(al, aad + TILE_ELE * 2);
#pragma unroll
                for (int nt = 0; nt < 4; nt++) {
                    float* c = &acc[(mt * 4 + nt) * 4];
                    mma16816(c, ah, &bh[nt * 2]);
                    mma16816(c, ah, &bl[nt * 2]);
                    mma16816(c, al, &bh[nt * 2]);
                }
            }
        }
        __syncthreads();
    }

    // ---- epilogue ----
#pragma unroll
    for (int mt = 0; mt < 4; mt++) {
        int r0 = m0 + wm * 64 + mt * 16 + (lane >> 2);
        int r1 = r0 + 8;
#pragma unroll
        for (int nt = 0; nt < 4; nt++) {
            const float* c = &acc[(mt * 4 + nt) * 4];
            int cb = n0 + wn * 32 + nt * 8 + ((lane & 3) << 1);
            if (mode == 0) {
                if (r0 < M) *(float2*)(Cf + (size_t)r0 * kD + cb) = make_float2(c[0], c[1]);
                if (r1 < M) *(float2*)(Cf + (size_t)r1 * kD + cb) = make_float2(c[2], c[3]);
            } else {
                float bv0 = bias[cb], bv1 = bias[cb + 1];
                if (r0 < M) {
                    float v0 = fmaxf(c[0] + bv0, 0.f), v1 = fmaxf(c[1] + bv1, 0.f);
                    __nv_bfloat16 h0, l0, h1, l1;
                    split2(v0, h0, l0); split2(v1, h1, l1);
                    *(__nv_bfloat162*)(Chi + (size_t)r0 * kD + cb) = __halves2bfloat162(h0, h1);
                    *(__nv_bfloat162*)(Clo + (size_t)r0 * kD + cb) = __halves2bfloat162(l0, l1);
                }
                if (r1 < M) {
                    float v0 = fmaxf(c[2] + bv0, 0.f), v1 = fmaxf(c[3] + bv1, 0.f);
                    __nv_bfloat16 h0, l0, h1, l1;
                    split2(v0, h0, l0); split2(v1, h1, l1);
                    *(__nv_bfloat162*)(Chi + (size_t)r1 * kD + cb) = __halves2bfloat162(h0, h1);
                    *(__nv_bfloat162*)(Clo + (size_t)r1 * kD + cb) = __halves2bfloat162(l0, l1);
                }
            }
        }
    }
}

// ============================ aggregation ============================
__global__ void k_agg_init(const float* __restrict__ b) {
    long long idx = (long long)blockIdx.x * blockDim.x + threadIdx.x;
    if (idx >= (long long)kN * 64) return;
    int i = (int)(idx >> 6);
    int d4 = (int)(idx & 63);
    float s = g_dinv[i]; s = s * s;
    float4 h4 = ((const float4*)g_h)[idx];
    float4 b4 = ((const float4*)b)[d4];
    ((float4*)g_y)[idx] = make_float4(h4.x * s + b4.x, h4.y * s + b4.y,
                                      h4.z * s + b4.z, h4.w * s + b4.w);
}

__global__ void k_agg_edges(const int* __restrict__ row, const int* __restrict__ col) {
    long long t = (long long)blockIdx.x * blockDim.x + threadIdx.x;
    int e = (int)(t >> 5);
    int lane = (int)(t & 31);
    if (e >= kE) return;
    int r = row[e], c = col[e];
    float nrm = g_dinv[r] * g_dinv[c];
    const float4* hp = (const float4*)(g_h + (size_t)c * kD);
    float4* yp = (float4*)(g_y + (size_t)r * kD);
#pragma unroll
    for (int j = 0; j < 2; j++) {
        float4 v = hp[lane + j * 32];
        float4 mv = make_float4(v.x * nrm, v.y * nrm, v.z * nrm, v.w * nrm);
        atomicAdd(yp + lane + j * 32, mv);
    }
}

__global__ void k_relu_split() {
    long long idx = (long long)blockIdx.x * blockDim.x + threadIdx.x;
    if (idx >= (long long)kN * 64) return;
    float4 v = ((const float4*)g_y)[idx];
    v.x = fmaxf(v.x, 0.f); v.y = fmaxf(v.y, 0.f);
    v.z = fmaxf(v.z, 0.f); v.w = fmaxf(v.w, 0.f);
    __nv_bfloat16 h0, h1, h2, h3, l0, l1, l2, l3;
    split2(v.x, h0, l0); split2(v.y, h1, l1); split2(v.z, h2, l2); split2(v.w, h3, l3);
    __nv_bfloat162* ph = (__nv_bfloat162*)g_x_hi;
    __nv_bfloat162* pl = (__nv_bfloat162*)g_x_lo;
    ph[idx * 2]     = __halves2bfloat162(h0, h1);
    ph[idx * 2 + 1] = __halves2bfloat162(h2, h3);
    pl[idx * 2]     = __halves2bfloat162(l0, l1);
    pl[idx * 2 + 1] = __halves2bfloat162(l2, l3);
}

// ============================ query gather (x[e0]*x[e1] -> hi/lo) ============================
__global__ void k_gather(const int* __restrict__ e0, const int* __restrict__ e1) {
    long long idx = (long long)blockIdx.x * blockDim.x + threadIdx.x;
    if (idx >= (long long)kQ * 64) return;
    int q = (int)(idx >> 6);
    int d4 = (int)(idx & 63);
    int a = e0[q], b = e1[q];
    float4 xa = ((const float4*)g_y)[(size_t)a * 64 + d4];
    float4 xb = ((const float4*)g_y)[(size_t)b * 64 + d4];
    float4 p = make_float4(xa.x * xb.x, xa.y * xb.y, xa.z * xb.z, xa.w * xb.w);
    __nv_bfloat16 h0, h1, h2, h3, l0, l1, l2, l3;
    split2(p.x, h0, l0); split2(p.y, h1, l1); split2(p.z, h2, l2); split2(p.w, h3, l3);
    __nv_bfloat162* ph = (__nv_bfloat162*)g_qa_hi;
    __nv_bfloat162* pl = (__nv_bfloat162*)g_qa_lo;
    ph[idx * 2]     = __halves2bfloat162(h0, h1);
    ph[idx * 2 + 1] = __halves2bfloat162(h2, h3);
    pl[idx * 2]     = __halves2bfloat162(l0, l1);
    pl[idx * 2 + 1] = __halves2bfloat162(l2, l3);
}

// ============================ final dot + sigmoid ============================
__global__ void k_final(const float* __restrict__ P2, const float* __restrict__ pb2,
                        float* __restrict__ out) {
    long long t = (long long)blockIdx.x * blockDim.x + threadIdx.x;
    int q = (int)(t >> 5);
    int lane = (int)(t & 31);
    if (q >= kQ) return;
    uint4 hv = ((const uint4*)(g_qa_hi + (size_t)q * kD))[lane];
    uint4 lv = ((const uint4*)(g_qa_lo + (size_t)q * kD))[lane];
    const float4* wp = (const float4*)P2;
    float4 w0 = wp[lane * 2], w1 = wp[lane * 2 + 1];
    const __nv_bfloat162* h2 = (const __nv_bfloat162*)&hv;
    const __nv_bfloat162* l2 = (const __nv_bfloat162*)&lv;
    float s = 0.f;
    float2 a;
    a = __bfloat1622float2(h2[0]); { float2 b = __bfloat1622float2(l2[0]); a.x += b.x; a.y += b.y; }
    s = fmaf(a.x, w0.x, s); s = fmaf(a.y, w0.y, s);
    a = __bfloat1622float2(h2[1]); { float2 b = __bfloat1622float2(l2[1]); a.x += b.x; a.y += b.y; }
    s = fmaf(a.x, w0.z, s); s = fmaf(a.y, w0.w, s);
    a = __bfloat1622float2(h2[2]); { float2 b = __bfloat1622float2(l2[2]); a.x += b.x; a.y += b.y; }
    s = fmaf(a.x, w1.x, s); s = fmaf(a.y, w1.y, s);
    a = __bfloat1622float2(h2[3]); { float2 b = __bfloat1622float2(l2[3]); a.x += b.x; a.y += b.y; }
    s = fmaf(a.x, w1.z, s); s = fmaf(a.y, w1.w, s);
#pragma unroll
    for (int o = 16; o > 0; o >>= 1) s += __shfl_down_sync(0xffffffffu, s, o);
    if (lane == 0) out[q] = 1.f / (1.f + expf(-(s + pb2[0])));
}

// ============================ launch ============================
extern "C" void kernel_launch(void* const* d_in, const int* in_sizes, int n_in,
                              void* d_out, int out_size) {
    const int*   adj_row = (const int*)d_in[0];
    const int*   adj_col = (const int*)d_in[1];
    const int*   edges   = (const int*)d_in[2];
    const float* emb     = (const float*)d_in[3];
    const float* W0 = (const float*)d_in[4];  const float* b0 = (const float*)d_in[5];
    const float* W1 = (const float*)d_in[6];  const float* b1 = (const float*)d_in[7];
    const float* W2 = (const float*)d_in[8];  const float* b2 = (const float*)d_in[9];
    const float* P0 = (const float*)d_in[10]; const float* pb0 = (const float*)d_in[11];
    const float* P1 = (const float*)d_in[12]; const float* pb1 = (const float*)d_in[13];
    const float* P2 = (const float*)d_in[14]; const float* pb2 = (const float*)d_in[15];
    float* out = (float*)d_out;

    cudaFuncSetAttribute(k_tc_gemm, cudaFuncAttributeMaxDynamicSharedMemorySize, SMEM_BYTES);

    float* dH;
    __nv_bfloat16 *dXh, *dXl, *dQah, *dQal, *dQbh, *dQbl, *dWth, *dWtl;
    cudaGetSymbolAddress((void**)&dH,   g_h);
    cudaGetSymbolAddress((void**)&dXh,  g_x_hi);
    cudaGetSymbolAddress((void**)&dXl,  g_x_lo);
    cudaGetSymbolAddress((void**)&dQah, g_qa_hi);
    cudaGetSymbolAddress((void**)&dQal, g_qa_lo);
    cudaGetSymbolAddress((void**)&dQbh, g_qb_hi);
    cudaGetSymbolAddress((void**)&dQbl, g_qb_lo);
    cudaGetSymbolAddress((void**)&dWth, g_wt_hi);
    cudaGetSymbolAddress((void**)&dWtl, g_wt_lo);

    const int TB = 256;
    k_deg_init<<<(kN + TB - 1) / TB, TB>>>();
    k_deg_count<<<(kE + TB - 1) / TB, TB>>>(adj_row);
    k_dinv<<<(kN + TB - 1) / TB, TB>>>();
    k_conv_w<<<(5 * kD * kD + TB - 1) / TB, TB>>>(W0, W1, W2, P0, P1);

    long long nEl = (long long)kN * 64;
    int gElem = (int)((nEl + TB - 1) / TB);
    int gEdge = (int)(((long long)kE * 32 + TB - 1) / TB);
    k_conv_emb<<<gElem, TB>>>(emb);

    dim3 gN((kN + BM - 1) / BM, 2);
    dim3 gQ((kQ + BM - 1) / BM, 2);
    const float* biasN[3] = {b0, b1, b2};

    for (int l = 0; l < 3; l++) {
        k_tc_gemm<<<gN, 256, SMEM_BYTES>>>(dXh, dXl, dWth + l * kD * kD, dWtl + l * kD * kD,
                                           kN, nullptr, 0, dH, nullptr, nullptr);
        k_agg_init<<<gElem, TB>>>(biasN[l]);
        k_agg_edges<<<gEdge, TB>>>(adj_row, adj_col);
        if (l < 2) k_relu_split<<<gElem, TB>>>();
    }

    long long qEl = (long long)kQ * 64;
    int gQel = (int)((qEl + TB - 1) / TB);
    k_gather<<<gQel, TB>>>(edges, edges + kQ);

    k_tc_gemm<<<gQ, 256, SMEM_BYTES>>>(dQah, dQal, dWth + 3 * kD * kD, dWtl + 3 * kD * kD,
                                       kQ, pb0, 1, nullptr, dQbh, dQbl);
    k_tc_gemm<<<gQ, 256, SMEM_BYTES>>>(dQbh, dQbl, dWth + 4 * kD * kD, dWtl + 4 * kD * kD,
                                       kQ, pb1, 1, nullptr, dQah, dQal);

    int gFin = (int)(((long long)kQ * 32 + TB - 1) / TB);
    k_final<<<gFin, TB>>>(P2, pb2, out);
}